// round 16
// baseline (speedup 1.0000x reference)
#include <cuda_runtime.h>
#include <cuda_bf16.h>
#include <cstdint>
#include <math.h>

// B = H = IN = 256, c = 1. Dead code (Wh*/Uh*, r_point_h) skipped.
// Single fused kernel, 128 blocks x 256 threads, dynamic smem.
// Phase 1: split-precision bf16 HMMA (mma.sync m16n8k16) GEMM 64x32x256 per block.
// Grid barrier. Phase 2: gates + cell update (R10-validated).

#define NB 256
#define MAXN 0.996f
#define EPSN 1e-15f
#define CLIPV 0.9999999f
#define NBLOCKS 128u
#define PITCH 264             // bf16 elems per smem row (528 B, ldmatrix conflict-free)

// dynamic smem byte offsets
#define XHI 0
#define XLO (XHI + 64 * PITCH * 2)       // 33792
#define ZHI (XLO + 64 * PITCH * 2)       // 67584
#define ZLO (ZHI + 32 * PITCH * 2)       // 84480
#define STAT (ZLO + 32 * PITCH * 2)      // 101376
#define SMEM_REQ (STAT + 1024)

__device__ float g_w[4][NB * NB];
__device__ float g_part[4][NB][8];
__device__ unsigned g_cnt;   // zero-init
__device__ unsigned g_gen;   // zero-init

// ---------------- fast math ---------------------------------------------------
__device__ __forceinline__ float fsqrt_(float x) { float r; asm("sqrt.approx.f32 %0,%1;" : "=f"(r) : "f"(x)); return r; }
__device__ __forceinline__ float frcp_(float x)  { float r; asm("rcp.approx.f32 %0,%1;"  : "=f"(r) : "f"(x)); return r; }
__device__ __forceinline__ float ftanh_(float x) { float e = __expf(2.0f * x); return 1.0f - 2.0f * frcp_(e + 1.0f); }
__device__ __forceinline__ float fatanh_(float x){ return 0.5f * __logf((1.0f + x) * frcp_(1.0f - x)); }
__device__ __forceinline__ float fasinh_(float x){ float a = fabsf(x); float l = __logf(a + fsqrt_(fmaf(a, a, 1.0f))); return copysignf(l, x); }
__device__ __forceinline__ float fsinh_(float x) { float e = __expf(x); return 0.5f * (e - frcp_(e)); }
__device__ __forceinline__ float fsigm_(float x) { return frcp_(1.0f + __expf(-x)); }

// ---------------- HMMA helpers -------------------------------------------------
__device__ __forceinline__ void ldsm4(unsigned addr, unsigned r[4]) {
    asm volatile("ldmatrix.sync.aligned.m8n8.x4.shared.b16 {%0,%1,%2,%3}, [%4];"
        : "=r"(r[0]), "=r"(r[1]), "=r"(r[2]), "=r"(r[3]) : "r"(addr));
}
__device__ __forceinline__ void mma16816(float c[4], const unsigned a[4],
                                         unsigned b0, unsigned b1) {
    asm volatile("mma.sync.aligned.m16n8k16.row.col.f32.bf16.bf16.f32 "
        "{%0,%1,%2,%3}, {%4,%5,%6,%7}, {%8,%9}, {%0,%1,%2,%3};"
        : "+f"(c[0]), "+f"(c[1]), "+f"(c[2]), "+f"(c[3])
        : "r"(a[0]), "r"(a[1]), "r"(a[2]), "r"(a[3]), "r"(b0), "r"(b1));
}

// ---------------- grid barrier ------------------------------------------------
__device__ __forceinline__ void grid_bar()
{
    __threadfence();
    __syncthreads();
    if (threadIdx.x == 0) {
        unsigned gen = *(volatile unsigned*)&g_gen;
        unsigned t = atomicAdd(&g_cnt, 1u);
        if (t == NBLOCKS - 1u) {
            *(volatile unsigned*)&g_cnt = 0u;
            __threadfence();
            *(volatile unsigned*)&g_gen = gen + 1u;
        } else {
            while (*(volatile unsigned*)&g_gen == gen) { }
        }
        __threadfence();
    }
    __syncthreads();
}

// ---------------- mlr/sinh epilogue -------------------------------------------
__device__ __forceinline__ float fc_elem(float nz, float inz, float coef,
                                         float rb, float y2b, float g)
{
    const float s  = g * inz;
    float alpha = ftanh_(rb * nz);
    float aa = fabsf(alpha);
    if (aa > MAXN) alpha *= MAXN * frcp_(aa);
    const float x2 = alpha * alpha;
    const float xy = -alpha * s;
    const float A  = 1.0f + 2.0f * xy + y2b;
    const float Bc = 1.0f - x2;
    const float den = fmaxf(1.0f + 2.0f * xy + x2 * y2b, EPSN);
    const float inv = frcp_(den);
    float pa = (Bc * s - A * alpha) * inv;
    float p2 = (A * A * x2 - 2.0f * A * Bc * alpha * s + Bc * Bc * y2b) * (inv * inv);
    float pn = fmaxf(fsqrt_(fmaxf(p2, 0.0f)), EPSN);
    if (pn > MAXN) { float f = MAXN * frcp_(pn); pa *= f; p2 *= f * f; }
    const float lam = 2.0f * frcp_(1.0f - p2);
    return fsinh_(coef * fasinh_(pa * lam));
}

// ---------------- madd scalar helper ------------------------------------------
struct MS { float A, B, inv, m, nc; };
__device__ __forceinline__ MS madds(float sxx, float syy, float sxy)
{
    MS r;
    r.A = 1.0f + 2.0f * sxy + syy;
    r.B = 1.0f - sxx;
    float den = fmaxf(1.0f + 2.0f * sxy + sxx * syy, EPSN);
    r.inv = frcp_(den);
    float n2 = (r.A * r.A * sxx + 2.0f * r.A * r.B * sxy + r.B * r.B * syy) * r.inv * r.inv;
    float n = fmaxf(fsqrt_(fmaxf(n2, 0.0f)), EPSN);
    r.m = (n > MAXN) ? MAXN * frcp_(n) : 1.0f;
    r.nc = fminf(n, MAXN);
    return r;
}

// ---------------- fused kernel ------------------------------------------------
extern __shared__ char dsm[];

__global__ void __launch_bounds__(256) fused_cell(
    const float* __restrict__ hidden, const float* __restrict__ hyp_x,
    const float* __restrict__ Wz_z, const float* __restrict__ Wz_r,
    const float* __restrict__ Uz_z, const float* __restrict__ Uz_r,
    const float* __restrict__ Wr_z, const float* __restrict__ Wr_r,
    const float* __restrict__ Ur_z, const float* __restrict__ Ur_r,
    const float* __restrict__ bz, const float* __restrict__ br,
    const float* __restrict__ bh, float* __restrict__ out)
{
    __shared__ float s_scale[4][NB];
    __shared__ float smr1[2][4][15];
    __shared__ float smr2[2][4][4];
    __shared__ float smr3[2][4][2];

    const int tid = threadIdx.x;
    const int bid = blockIdx.x;
    const int lane = tid & 31, wid = tid >> 5;
    const unsigned base = (unsigned)__cvta_generic_to_shared(dsm);

    // ============= PHASE 1: GEMM + epilogue ====================================
    {
        const int fc = bid >> 5, my = (bid >> 3) & 3, nx = bid & 7;
        const float *X, *Z, *R;
        if      (fc == 0) { X = hidden; Z = Wz_z; R = Wz_r; }
        else if (fc == 1) { X = hyp_x;  Z = Uz_z; R = Uz_r; }
        else if (fc == 2) { X = hidden; Z = Wr_z; R = Wr_r; }
        else              { X = hyp_x;  Z = Ur_z; R = Ur_r; }
        const int b0 = my * 64, c0 = nx * 32;

        float* sXr = (float*)(dsm + STAT);     // [64]
        float* sZr = sXr + 64;                 // [32]
        float* nzv = sZr + 32;                 // [32]
        float* izv = nzv + 32;                 // [32]
        float* cfv = izv + 32;                 // [32]

        // ---- convert X tile (64x256) to bf16 hi/lo ----
        const float2* Xg2 = reinterpret_cast<const float2*>(X);
        for (int i = tid; i < 8192; i += 256) {
            const int row = i >> 7, c2 = i & 127;
            float2 v = Xg2[(b0 + row) * 128 + c2];
            __nv_bfloat16 hx = __float2bfloat16(v.x), hy = __float2bfloat16(v.y);
            __nv_bfloat16 lx = __float2bfloat16(v.x - __bfloat162float(hx));
            __nv_bfloat16 ly = __float2bfloat16(v.y - __bfloat162float(hy));
            const int off = (row * PITCH + c2 * 2) * 2;
            *reinterpret_cast<__nv_bfloat162*>(dsm + XHI + off) = __nv_bfloat162(hx, hy);
            *reinterpret_cast<__nv_bfloat162*>(dsm + XLO + off) = __nv_bfloat162(lx, ly);
        }
        // ---- convert Z tile (32x256) ----
        const float2* Zg2 = reinterpret_cast<const float2*>(Z);
        for (int i = tid; i < 4096; i += 256) {
            const int row = i >> 7, c2 = i & 127;
            float2 v = Zg2[(c0 + row) * 128 + c2];
            __nv_bfloat16 hx = __float2bfloat16(v.x), hy = __float2bfloat16(v.y);
            __nv_bfloat16 lx = __float2bfloat16(v.x - __bfloat162float(hx));
            __nv_bfloat16 ly = __float2bfloat16(v.y - __bfloat162float(hy));
            const int off = (row * PITCH + c2 * 2) * 2;
            *reinterpret_cast<__nv_bfloat162*>(dsm + ZHI + off) = __nv_bfloat162(hx, hy);
            *reinterpret_cast<__nv_bfloat162*>(dsm + ZLO + off) = __nv_bfloat162(lx, ly);
        }
        // ---- row stats (fp32, warp per row) ----
        const float4* Xg4 = reinterpret_cast<const float4*>(X);
        for (int r = wid; r < 64; r += 8) {
            float4 u = Xg4[(b0 + r) * 64 + lane];
            float4 w = Xg4[(b0 + r) * 64 + 32 + lane];
            float s = u.x*u.x + u.y*u.y + u.z*u.z + u.w*u.w
                    + w.x*w.x + w.y*w.y + w.z*w.z + w.w*w.w;
            #pragma unroll
            for (int o = 16; o; o >>= 1) s += __shfl_xor_sync(0xffffffffu, s, o);
            if (lane == 0) sXr[r] = s;
        }
        const float4* Zg4 = reinterpret_cast<const float4*>(Z);
        for (int r = wid; r < 32; r += 8) {
            float4 u = Zg4[(c0 + r) * 64 + lane];
            float4 w = Zg4[(c0 + r) * 64 + 32 + lane];
            float s = u.x*u.x + u.y*u.y + u.z*u.z + u.w*u.w
                    + w.x*w.x + w.y*w.y + w.z*w.z + w.w*w.w;
            #pragma unroll
            for (int o = 16; o; o >>= 1) s += __shfl_xor_sync(0xffffffffu, s, o);
            if (lane == 0) sZr[r] = s;
        }
        __syncthreads();
        if (tid < 32) {
            float nz = sqrtf(sZr[tid]);
            nzv[tid] = nz; izv[tid] = frcp_(nz);
            float e = __expf(R[c0 + tid]);
            float ch = 0.5f * (e + frcp_(e));
            cfv[tid] = 2.0f * nz * frcp_(ch * ch);
        }
        __syncthreads();

        // ---- HMMA loop: warp w -> m16 at (w&3)*16, n16 at (w>>2)*16 ----
        const int m0 = (wid & 3) * 16, n0 = (wid >> 2) * 16;
        float c0f[4] = {0.f,0.f,0.f,0.f}, c1f[4] = {0.f,0.f,0.f,0.f};

        const unsigned aoff = (unsigned)(((m0 + (lane & 15)) * PITCH + ((lane >> 4) * 8)) * 2);
        const unsigned boff = (unsigned)(((n0 + (lane & 15)) * PITCH + ((lane >> 4) * 8)) * 2);
        const unsigned aHi = base + XHI + aoff, aLo = base + XLO + aoff;
        const unsigned bHi = base + ZHI + boff, bLo = base + ZLO + boff;

        #pragma unroll
        for (int ks = 0; ks < 16; ks++) {
            const unsigned kb = ks * 32;   // 16 bf16 = 32 bytes
            unsigned ah[4], al[4], zh[4], zl[4];
            ldsm4(aHi + kb, ah);
            ldsm4(aLo + kb, al);
            ldsm4(bHi + kb, zh);
            ldsm4(bLo + kb, zl);
            // n-half 0: B = {r0, r2}; n-half 1: B = {r1, r3}
            mma16816(c0f, ah, zh[0], zh[2]);
            mma16816(c0f, ah, zl[0], zl[2]);
            mma16816(c0f, al, zh[0], zh[2]);
            mma16816(c1f, ah, zh[1], zh[3]);
            mma16816(c1f, ah, zl[1], zl[3]);
            mma16816(c1f, al, zh[1], zh[3]);
        }
        __syncthreads();   // all smem reads done; reuse XHI region as D staging

        // ---- write C fragments to smem Dst[64][32] ----
        float* Dst = (float*)(dsm + XHI);
        {
            const int mr = lane >> 2, nc2 = (lane & 3) * 2;
            *reinterpret_cast<float2*>(&Dst[(m0 + mr) * 32 + n0 + nc2])         = make_float2(c0f[0], c0f[1]);
            *reinterpret_cast<float2*>(&Dst[(m0 + mr + 8) * 32 + n0 + nc2])     = make_float2(c0f[2], c0f[3]);
            *reinterpret_cast<float2*>(&Dst[(m0 + mr) * 32 + n0 + 8 + nc2])     = make_float2(c1f[0], c1f[1]);
            *reinterpret_cast<float2*>(&Dst[(m0 + mr + 8) * 32 + n0 + 8 + nc2]) = make_float2(c1f[2], c1f[3]);
        }
        __syncthreads();

        // ---- epilogue: thread -> row m = tid>>2, 8 cols ----
        {
            const int m = tid >> 2, q = tid & 3;
            const float rb = R[b0 + m];
            const float y2 = sXr[m];
            float* gw = &g_w[fc][(b0 + m) * 256 + c0];
            float psum = 0.f;
            #pragma unroll
            for (int j = 0; j < 8; j++) {
                const int n = q * 8 + j;
                float w = fc_elem(nzv[n], izv[n], cfv[n], rb, y2, Dst[m * 32 + n]);
                gw[n] = w;
                psum = fmaf(w, w, psum);
            }
            psum += __shfl_xor_sync(0xffffffffu, psum, 1);
            psum += __shfl_xor_sync(0xffffffffu, psum, 2);
            if (q == 0) g_part[fc][b0 + m][nx] = psum;
        }
    }

    // ============= GRID BARRIER ================================================
    grid_bar();

    // ============= PHASE 2: scales + gates + cell update (R10-validated) =======
    #pragma unroll
    for (int r = 0; r < 4; r++) {
        const int idx = tid + 256 * r;
        const int q = idx >> 8, row = idx & 255;
        const float4* p4 = reinterpret_cast<const float4*>(g_part[q][row]);
        float4 u0 = p4[0], u1 = p4[1];
        s_scale[q][row] = sqrtf(u0.x + u0.y + u0.z + u0.w + u1.x + u1.y + u1.z + u1.w) + 1.0f;
    }
    __syncthreads();

    const int half = tid >> 7;
    const int lt   = tid & 127;
    const int wih  = (tid >> 5) & 3;
    const int b    = bid * 2 + half;

    float hid[2], bhv[2], bzv[2], brv[2], F0[2], G0[2], F1[2], G1[2];
    #pragma unroll
    for (int i = 0; i < 2; i++) {
        const int j = lt + 128 * i;
        hid[i] = hidden[b * NB + j];
        bhv[i] = bh[j]; bzv[i] = bz[j]; brv[i] = br[j];
        F0[i] = s_scale[0][j] * g_w[0][b * NB + j];
        G0[i] = s_scale[1][j] * g_w[1][b * NB + j];
        F1[i] = s_scale[2][j] * g_w[2][b * NB + j];
        G1[i] = s_scale[3][j] * g_w[3][b * NB + j];
    }

    float v[15];
    #pragma unroll
    for (int k = 0; k < 15; k++) v[k] = 0.0f;
    #pragma unroll
    for (int i = 0; i < 2; i++) {
        v[0]  = fmaf(F0[i], F0[i], v[0]);   v[1]  = fmaf(G0[i], G0[i], v[1]);
        v[2]  = fmaf(F0[i], G0[i], v[2]);   v[3]  = fmaf(F0[i], bzv[i], v[3]);
        v[4]  = fmaf(G0[i], bzv[i], v[4]);  v[5]  = fmaf(bzv[i], bzv[i], v[5]);
        v[6]  = fmaf(F1[i], F1[i], v[6]);   v[7]  = fmaf(G1[i], G1[i], v[7]);
        v[8]  = fmaf(F1[i], G1[i], v[8]);   v[9]  = fmaf(F1[i], brv[i], v[9]);
        v[10] = fmaf(G1[i], brv[i], v[10]); v[11] = fmaf(brv[i], brv[i], v[11]);
        v[12] = fmaf(hid[i], hid[i], v[12]);v[13] = fmaf(bhv[i], bhv[i], v[13]);
        v[14] = fmaf(hid[i], bhv[i], v[14]);
    }
    #pragma unroll
    for (int k = 0; k < 15; k++) {
        #pragma unroll
        for (int o = 16; o; o >>= 1) v[k] += __shfl_xor_sync(0xffffffffu, v[k], o);
    }
    if ((tid & 31) == 0) {
        #pragma unroll
        for (int k = 0; k < 15; k++) smr1[half][wih][k] = v[k];
    }
    __syncthreads();
    #pragma unroll
    for (int k = 0; k < 15; k++)
        v[k] = smr1[half][0][k] + smr1[half][1][k] + smr1[half][2][k] + smr1[half][3][k];

    const float sFF0 = v[0], sGG0 = v[1], sFG0 = v[2], sFb0 = v[3], sGb0 = v[4], sbb0 = v[5];
    const float sFF1 = v[6], sGG1 = v[7], sFG1 = v[8], sFb1 = v[9], sGb1 = v[10], sbb1 = v[11];
    const float shh = v[12], sbhbh = v[13], shbh = v[14];

    MS z1 = madds(sFF0, sGG0, sFG0);
    float zcF = z1.m * z1.inv * z1.A, zcG = z1.m * z1.inv * z1.B;
    MS z2 = madds(z1.nc * z1.nc, sbb0, zcF * sFb0 + zcG * sGb0);
    float k2a = z2.m * z2.inv * z2.A, k2b = z2.m * z2.inv * z2.B;
    float facz = fatanh_(z2.nc) * frcp_(z2.nc);
    float zg[2];
    #pragma unroll
    for (int i = 0; i < 2; i++)
        zg[i] = fsigm_(facz * (k2a * (zcF * F0[i] + zcG * G0[i]) + k2b * bzv[i]));

    MS r1 = madds(sFF1, sGG1, sFG1);
    float rcF = r1.m * r1.inv * r1.A, rcG = r1.m * r1.inv * r1.B;
    MS r2 = madds(r1.nc * r1.nc, sbb1, rcF * sFb1 + rcG * sGb1);
    float l2a = r2.m * r2.inv * r2.A, l2b = r2.m * r2.inv * r2.B;
    float facr = fatanh_(r2.nc) * frcp_(r2.nc);
    float rg[2];
    #pragma unroll
    for (int i = 0; i < 2; i++)
        rg[i] = fsigm_(facr * (l2a * (rcF * F1[i] + rcG * G1[i]) + l2b * brv[i]));

    float v2[4] = {0.f, 0.f, 0.f, 0.f};
    #pragma unroll
    for (int i = 0; i < 2; i++) {
        v2[0] = fmaf(rg[i], rg[i], v2[0]);  v2[1] = fmaf(rg[i], bhv[i], v2[1]);
        v2[2] = fmaf(hid[i], rg[i], v2[2]); v2[3] = fmaf(zg[i], zg[i], v2[3]);
    }
    #pragma unroll
    for (int k = 0; k < 4; k++) {
        #pragma unroll
        for (int o = 16; o; o >>= 1) v2[k] += __shfl_xor_sync(0xffffffffu, v2[k], o);
    }
    if ((tid & 31) == 0) {
        #pragma unroll
        for (int k = 0; k < 4; k++) smr2[half][wih][k] = v2[k];
    }
    __syncthreads();
    #pragma unroll
    for (int k = 0; k < 4; k++)
        v2[k] = smr2[half][0][k] + smr2[half][1][k] + smr2[half][2][k] + smr2[half][3][k];
    const float srr = v2[0], srbh = v2[1], shr = v2[2], szz = v2[3];

    MS h3 = madds(srr, sbhbh, srbh);
    float hA = h3.m * h3.inv * h3.A, hB = h3.m * h3.inv * h3.B;
    float sht_h = hA * shr + hB * shbh;
    MS h4 = madds(shh, h3.nc * h3.nc, -sht_h);
    float mA = -h4.m * h4.inv * h4.A;
    float mR =  h4.m * h4.inv * h4.B * hA;
    float mB =  h4.m * h4.inv * h4.B * hB;

    float wx[2];
    float v3[2] = {0.f, 0.f};
    #pragma unroll
    for (int i = 0; i < 2; i++) {
        wx[i] = (mA * hid[i] + mR * rg[i] + mB * bhv[i]) * zg[i];
        v3[0] = fmaf(wx[i], wx[i], v3[0]);
        v3[1] = fmaf(hid[i], wx[i], v3[1]);
    }
    #pragma unroll
    for (int k = 0; k < 2; k++) {
        #pragma unroll
        for (int o = 16; o; o >>= 1) v3[k] += __shfl_xor_sync(0xffffffffu, v3[k], o);
    }
    if ((tid & 31) == 0) {
        #pragma unroll
        for (int k = 0; k < 2; k++) smr3[half][wih][k] = v3[k];
    }
    __syncthreads();
    const float swx  = smr3[half][0][0] + smr3[half][1][0] + smr3[half][2][0] + smr3[half][3][0];
    const float shwx = smr3[half][0][1] + smr3[half][1][1] + smr3[half][2][1] + smr3[half][3][1];

    float xn  = fmaxf(fsqrt_(szz), EPSN);
    float wxn = fmaxf(fsqrt_(swx), EPSN);
    float tt  = fatanh_(fminf(xn, CLIPV));
    float f   = ftanh_(wxn * frcp_(xn) * tt);
    float pn  = fmaxf(f, EPSN);
    float cf  = f * frcp_(wxn);
    if (pn > MAXN) cf *= MAXN * frcp_(pn);
    float pnc = fminf(pn, MAXN);

    MS o5 = madds(shh, pnc * pnc, cf * shwx);
    float oH = o5.m * o5.inv * o5.A, oP = o5.m * o5.inv * o5.B * cf;

    #pragma unroll
    for (int i = 0; i < 2; i++)
        out[b * NB + lt + 128 * i] = oH * hid[i] + oP * wx[i];
}

// ---------------- launch ------------------------------------------------------
extern "C" void kernel_launch(void* const* d_in, const int* in_sizes, int n_in,
                              void* d_out, int out_size)
{
    const float* hyp_x  = (const float*)d_in[0];
    const float* hidden = (const float*)d_in[1];
    const float* Wz_z   = (const float*)d_in[2];
    const float* Wz_r   = (const float*)d_in[3];
    const float* Uz_z   = (const float*)d_in[4];
    const float* Uz_r   = (const float*)d_in[5];
    const float* Wr_z   = (const float*)d_in[6];
    const float* Wr_r   = (const float*)d_in[7];
    const float* Ur_z   = (const float*)d_in[8];
    const float* Ur_r   = (const float*)d_in[9];
    const float* b_z    = (const float*)d_in[14];
    const float* b_r    = (const float*)d_in[15];
    const float* b_h    = (const float*)d_in[16];
    float* out = (float*)d_out;

    cudaFuncSetAttribute(fused_cell, cudaFuncAttributeMaxDynamicSharedMemorySize, SMEM_REQ);
    fused_cell<<<NBLOCKS, 256, SMEM_REQ>>>(hidden, hyp_x, Wz_z, Wz_r, Uz_z, Uz_r,
                                           Wr_z, Wr_r, Ur_z, Ur_r, b_z, b_r, b_h, out);
}

// round 17
// speedup vs baseline: 1.4315x; 1.4315x over previous
#include <cuda_runtime.h>
#include <cuda_bf16.h>
#include <cstdint>
#include <math.h>

// B = H = IN = 256, c = 1. Dead code (Wh*/Uh*, r_point_h) skipped.
// Single fused kernel, 128 blocks x 256 threads, dynamic smem.
// Phase 1: split-precision bf16 HMMA (mma.sync m16n8k16) GEMM 64x32x256 per block,
//          single-pass fused convert+stats (warp-per-row, float4).
// Grid barrier. Phase 2: gates + cell update (validated).

#define NB 256
#define MAXN 0.996f
#define EPSN 1e-15f
#define CLIPV 0.9999999f
#define NBLOCKS 128u
#define PITCH 264             // bf16 elems per smem row (528 B)

#define XHI 0
#define XLO (XHI + 64 * PITCH * 2)
#define ZHI (XLO + 64 * PITCH * 2)
#define ZLO (ZHI + 32 * PITCH * 2)
#define STAT (ZLO + 32 * PITCH * 2)
#define SMEM_REQ (STAT + 1024)

__device__ float g_w[4][NB * NB];
__device__ float g_part[4][NB][8];
__device__ unsigned g_cnt;   // zero-init
__device__ unsigned g_gen;   // zero-init

// ---------------- fast math ---------------------------------------------------
__device__ __forceinline__ float fsqrt_(float x) { float r; asm("sqrt.approx.f32 %0,%1;" : "=f"(r) : "f"(x)); return r; }
__device__ __forceinline__ float frcp_(float x)  { float r; asm("rcp.approx.f32 %0,%1;"  : "=f"(r) : "f"(x)); return r; }
__device__ __forceinline__ float ftanh_(float x) { float e = __expf(2.0f * x); return 1.0f - 2.0f * frcp_(e + 1.0f); }
__device__ __forceinline__ float fatanh_(float x){ return 0.5f * __logf((1.0f + x) * frcp_(1.0f - x)); }
__device__ __forceinline__ float fasinh_(float x){ float a = fabsf(x); float l = __logf(a + fsqrt_(fmaf(a, a, 1.0f))); return copysignf(l, x); }
__device__ __forceinline__ float fsinh_(float x) { float e = __expf(x); return 0.5f * (e - frcp_(e)); }
__device__ __forceinline__ float fsigm_(float x) { return frcp_(1.0f + __expf(-x)); }

// ---------------- HMMA helpers -------------------------------------------------
__device__ __forceinline__ void ldsm4(unsigned addr, unsigned r[4]) {
    asm volatile("ldmatrix.sync.aligned.m8n8.x4.shared.b16 {%0,%1,%2,%3}, [%4];"
        : "=r"(r[0]), "=r"(r[1]), "=r"(r[2]), "=r"(r[3]) : "r"(addr));
}
__device__ __forceinline__ void mma16816(float c[4], const unsigned a[4],
                                         unsigned b0, unsigned b1) {
    asm volatile("mma.sync.aligned.m16n8k16.row.col.f32.bf16.bf16.f32 "
        "{%0,%1,%2,%3}, {%4,%5,%6,%7}, {%8,%9}, {%0,%1,%2,%3};"
        : "+f"(c[0]), "+f"(c[1]), "+f"(c[2]), "+f"(c[3])
        : "r"(a[0]), "r"(a[1]), "r"(a[2]), "r"(a[3]), "r"(b0), "r"(b1));
}

// convert float4 -> hi/lo bf16x4 and store (8B each)
__device__ __forceinline__ void cvt_store(char* pHi, char* pLo, float4 v) {
    __nv_bfloat16 h0 = __float2bfloat16(v.x), h1 = __float2bfloat16(v.y);
    __nv_bfloat16 h2 = __float2bfloat16(v.z), h3 = __float2bfloat16(v.w);
    __nv_bfloat16 l0 = __float2bfloat16(v.x - __bfloat162float(h0));
    __nv_bfloat16 l1 = __float2bfloat16(v.y - __bfloat162float(h1));
    __nv_bfloat16 l2 = __float2bfloat16(v.z - __bfloat162float(h2));
    __nv_bfloat16 l3 = __float2bfloat16(v.w - __bfloat162float(h3));
    reinterpret_cast<__nv_bfloat162*>(pHi)[0] = __nv_bfloat162(h0, h1);
    reinterpret_cast<__nv_bfloat162*>(pHi)[1] = __nv_bfloat162(h2, h3);
    reinterpret_cast<__nv_bfloat162*>(pLo)[0] = __nv_bfloat162(l0, l1);
    reinterpret_cast<__nv_bfloat162*>(pLo)[1] = __nv_bfloat162(l2, l3);
}

// ---------------- grid barrier ------------------------------------------------
__device__ __forceinline__ void grid_bar()
{
    __threadfence();
    __syncthreads();
    if (threadIdx.x == 0) {
        unsigned gen = *(volatile unsigned*)&g_gen;
        unsigned t = atomicAdd(&g_cnt, 1u);
        if (t == NBLOCKS - 1u) {
            *(volatile unsigned*)&g_cnt = 0u;
            __threadfence();
            *(volatile unsigned*)&g_gen = gen + 1u;
        } else {
            while (*(volatile unsigned*)&g_gen == gen) { }
        }
        __threadfence();
    }
    __syncthreads();
}

// ---------------- mlr/sinh epilogue -------------------------------------------
__device__ __forceinline__ float fc_elem(float nz, float inz, float coef,
                                         float rb, float y2b, float g)
{
    const float s  = g * inz;
    float alpha = ftanh_(rb * nz);
    float aa = fabsf(alpha);
    if (aa > MAXN) alpha *= MAXN * frcp_(aa);
    const float x2 = alpha * alpha;
    const float xy = -alpha * s;
    const float A  = 1.0f + 2.0f * xy + y2b;
    const float Bc = 1.0f - x2;
    const float den = fmaxf(1.0f + 2.0f * xy + x2 * y2b, EPSN);
    const float inv = frcp_(den);
    float pa = (Bc * s - A * alpha) * inv;
    float p2 = (A * A * x2 - 2.0f * A * Bc * alpha * s + Bc * Bc * y2b) * (inv * inv);
    float pn = fmaxf(fsqrt_(fmaxf(p2, 0.0f)), EPSN);
    if (pn > MAXN) { float f = MAXN * frcp_(pn); pa *= f; p2 *= f * f; }
    const float lam = 2.0f * frcp_(1.0f - p2);
    return fsinh_(coef * fasinh_(pa * lam));
}

// ---------------- madd scalar helper ------------------------------------------
struct MS { float A, B, inv, m, nc; };
__device__ __forceinline__ MS madds(float sxx, float syy, float sxy)
{
    MS r;
    r.A = 1.0f + 2.0f * sxy + syy;
    r.B = 1.0f - sxx;
    float den = fmaxf(1.0f + 2.0f * sxy + sxx * syy, EPSN);
    r.inv = frcp_(den);
    float n2 = (r.A * r.A * sxx + 2.0f * r.A * r.B * sxy + r.B * r.B * syy) * r.inv * r.inv;
    float n = fmaxf(fsqrt_(fmaxf(n2, 0.0f)), EPSN);
    r.m = (n > MAXN) ? MAXN * frcp_(n) : 1.0f;
    r.nc = fminf(n, MAXN);
    return r;
}

// ---------------- fused kernel ------------------------------------------------
extern __shared__ char dsm[];

__global__ void __launch_bounds__(256) fused_cell(
    const float* __restrict__ hidden, const float* __restrict__ hyp_x,
    const float* __restrict__ Wz_z, const float* __restrict__ Wz_r,
    const float* __restrict__ Uz_z, const float* __restrict__ Uz_r,
    const float* __restrict__ Wr_z, const float* __restrict__ Wr_r,
    const float* __restrict__ Ur_z, const float* __restrict__ Ur_r,
    const float* __restrict__ bz, const float* __restrict__ br,
    const float* __restrict__ bh, float* __restrict__ out)
{
    __shared__ float s_scale[4][NB];
    __shared__ float smr1[2][4][15];
    __shared__ float smr2[2][4][4];
    __shared__ float smr3[2][4][2];

    const int tid = threadIdx.x;
    const int bid = blockIdx.x;
    const int lane = tid & 31, wid = tid >> 5;
    const unsigned base = (unsigned)__cvta_generic_to_shared(dsm);

    // ============= PHASE 1: GEMM + epilogue ====================================
    {
        const int fc = bid >> 5, my = (bid >> 3) & 3, nx = bid & 7;
        const float *X, *Z, *R;
        if      (fc == 0) { X = hidden; Z = Wz_z; R = Wz_r; }
        else if (fc == 1) { X = hyp_x;  Z = Uz_z; R = Uz_r; }
        else if (fc == 2) { X = hidden; Z = Wr_z; R = Wr_r; }
        else              { X = hyp_x;  Z = Ur_z; R = Ur_r; }
        const int b0 = my * 64, c0 = nx * 32;

        float* sXr = (float*)(dsm + STAT);     // [64]
        float* sZr = sXr + 64;                 // [32]
        float* nzv = sZr + 32;                 // [32]
        float* izv = nzv + 32;                 // [32]
        float* cfv = izv + 32;                 // [32]

        // ---- single-pass convert + stats: warp per row, float4 loads ----
        const float4* Xg4 = reinterpret_cast<const float4*>(X);
        for (int r = wid; r < 64; r += 8) {
            float4 u = Xg4[(b0 + r) * 64 + lane];
            float4 w = Xg4[(b0 + r) * 64 + 32 + lane];
            float s = u.x*u.x + u.y*u.y + u.z*u.z + u.w*u.w
                    + w.x*w.x + w.y*w.y + w.z*w.z + w.w*w.w;
            #pragma unroll
            for (int o = 16; o; o >>= 1) s += __shfl_xor_sync(0xffffffffu, s, o);
            if (lane == 0) sXr[r] = s;
            const int offU = (r * PITCH + lane * 4) * 2;
            const int offW = (r * PITCH + lane * 4 + 128) * 2;
            cvt_store(dsm + XHI + offU, dsm + XLO + offU, u);
            cvt_store(dsm + XHI + offW, dsm + XLO + offW, w);
        }
        const float4* Zg4 = reinterpret_cast<const float4*>(Z);
        for (int r = wid; r < 32; r += 8) {
            float4 u = Zg4[(c0 + r) * 64 + lane];
            float4 w = Zg4[(c0 + r) * 64 + 32 + lane];
            float s = u.x*u.x + u.y*u.y + u.z*u.z + u.w*u.w
                    + w.x*w.x + w.y*w.y + w.z*w.z + w.w*w.w;
            #pragma unroll
            for (int o = 16; o; o >>= 1) s += __shfl_xor_sync(0xffffffffu, s, o);
            if (lane == 0) sZr[r] = s;
            const int offU = (r * PITCH + lane * 4) * 2;
            const int offW = (r * PITCH + lane * 4 + 128) * 2;
            cvt_store(dsm + ZHI + offU, dsm + ZLO + offU, u);
            cvt_store(dsm + ZHI + offW, dsm + ZLO + offW, w);
        }
        __syncthreads();
        if (tid < 32) {
            float nz = sqrtf(sZr[tid]);
            nzv[tid] = nz; izv[tid] = frcp_(nz);
            float e = __expf(R[c0 + tid]);
            float ch = 0.5f * (e + frcp_(e));
            cfv[tid] = 2.0f * nz * frcp_(ch * ch);
        }
        __syncthreads();

        // ---- HMMA loop: warp w -> m16 at (w&3)*16, n16 at (w>>2)*16 ----
        const int m0 = (wid & 3) * 16, n0 = (wid >> 2) * 16;
        float c0f[4] = {0.f,0.f,0.f,0.f}, c1f[4] = {0.f,0.f,0.f,0.f};

        const unsigned aoff = (unsigned)(((m0 + (lane & 15)) * PITCH + ((lane >> 4) * 8)) * 2);
        const unsigned boff = (unsigned)(((n0 + (lane & 15)) * PITCH + ((lane >> 4) * 8)) * 2);
        const unsigned aHi = base + XHI + aoff, aLo = base + XLO + aoff;
        const unsigned bHi = base + ZHI + boff, bLo = base + ZLO + boff;

        #pragma unroll
        for (int ks = 0; ks < 16; ks++) {
            const unsigned kb = ks * 32;
            unsigned ah[4], al[4], zh[4], zl[4];
            ldsm4(aHi + kb, ah);
            ldsm4(aLo + kb, al);
            ldsm4(bHi + kb, zh);
            ldsm4(bLo + kb, zl);
            mma16816(c0f, ah, zh[0], zh[2]);
            mma16816(c0f, ah, zl[0], zl[2]);
            mma16816(c0f, al, zh[0], zh[2]);
            mma16816(c1f, ah, zh[1], zh[3]);
            mma16816(c1f, ah, zl[1], zl[3]);
            mma16816(c1f, al, zh[1], zh[3]);
        }
        __syncthreads();   // all smem reads done; reuse XHI region as D staging

        // ---- write C fragments to smem Dst[64][32] ----
        float* Dst = (float*)(dsm + XHI);
        {
            const int mr = lane >> 2, nc2 = (lane & 3) * 2;
            *reinterpret_cast<float2*>(&Dst[(m0 + mr) * 32 + n0 + nc2])         = make_float2(c0f[0], c0f[1]);
            *reinterpret_cast<float2*>(&Dst[(m0 + mr + 8) * 32 + n0 + nc2])     = make_float2(c0f[2], c0f[3]);
            *reinterpret_cast<float2*>(&Dst[(m0 + mr) * 32 + n0 + 8 + nc2])     = make_float2(c1f[0], c1f[1]);
            *reinterpret_cast<float2*>(&Dst[(m0 + mr + 8) * 32 + n0 + 8 + nc2]) = make_float2(c1f[2], c1f[3]);
        }
        __syncthreads();

        // ---- epilogue: thread -> row m = tid>>2, 8 cols ----
        {
            const int m = tid >> 2, q = tid & 3;
            const float rb = R[b0 + m];
            const float y2 = sXr[m];
            float* gw = &g_w[fc][(b0 + m) * 256 + c0];
            float psum = 0.f;
            #pragma unroll
            for (int j = 0; j < 8; j++) {
                const int n = q * 8 + j;
                float w = fc_elem(nzv[n], izv[n], cfv[n], rb, y2, Dst[m * 32 + n]);
                gw[n] = w;
                psum = fmaf(w, w, psum);
            }
            psum += __shfl_xor_sync(0xffffffffu, psum, 1);
            psum += __shfl_xor_sync(0xffffffffu, psum, 2);
            if (q == 0) g_part[fc][b0 + m][nx] = psum;
        }
    }

    // ---- preload phase-2 inputs independent of phase 1 (hide under barrier) ---
    const int half = tid >> 7;
    const int lt   = tid & 127;
    const int wih  = (tid >> 5) & 3;
    const int b    = bid * 2 + half;
    float hid[2], bhv[2], bzv[2], brv[2];
    #pragma unroll
    for (int i = 0; i < 2; i++) {
        const int j = lt + 128 * i;
        hid[i] = hidden[b * NB + j];
        bhv[i] = bh[j]; bzv[i] = bz[j]; brv[i] = br[j];
    }

    // ============= GRID BARRIER ================================================
    grid_bar();

    // ============= PHASE 2: scales + gates + cell update =======================
    #pragma unroll
    for (int r = 0; r < 4; r++) {
        const int idx = tid + 256 * r;
        const int q = idx >> 8, row = idx & 255;
        const float4* p4 = reinterpret_cast<const float4*>(g_part[q][row]);
        float4 u0 = p4[0], u1 = p4[1];
        s_scale[q][row] = sqrtf(u0.x + u0.y + u0.z + u0.w + u1.x + u1.y + u1.z + u1.w) + 1.0f;
    }
    __syncthreads();

    float F0[2], G0[2], F1[2], G1[2];
    #pragma unroll
    for (int i = 0; i < 2; i++) {
        const int j = lt + 128 * i;
        F0[i] = s_scale[0][j] * g_w[0][b * NB + j];
        G0[i] = s_scale[1][j] * g_w[1][b * NB + j];
        F1[i] = s_scale[2][j] * g_w[2][b * NB + j];
        G1[i] = s_scale[3][j] * g_w[3][b * NB + j];
    }

    float v[15];
    #pragma unroll
    for (int k = 0; k < 15; k++) v[k] = 0.0f;
    #pragma unroll
    for (int i = 0; i < 2; i++) {
        v[0]  = fmaf(F0[i], F0[i], v[0]);   v[1]  = fmaf(G0[i], G0[i], v[1]);
        v[2]  = fmaf(F0[i], G0[i], v[2]);   v[3]  = fmaf(F0[i], bzv[i], v[3]);
        v[4]  = fmaf(G0[i], bzv[i], v[4]);  v[5]  = fmaf(bzv[i], bzv[i], v[5]);
        v[6]  = fmaf(F1[i], F1[i], v[6]);   v[7]  = fmaf(G1[i], G1[i], v[7]);
        v[8]  = fmaf(F1[i], G1[i], v[8]);   v[9]  = fmaf(F1[i], brv[i], v[9]);
        v[10] = fmaf(G1[i], brv[i], v[10]); v[11] = fmaf(brv[i], brv[i], v[11]);
        v[12] = fmaf(hid[i], hid[i], v[12]);v[13] = fmaf(bhv[i], bhv[i], v[13]);
        v[14] = fmaf(hid[i], bhv[i], v[14]);
    }
    #pragma unroll
    for (int k = 0; k < 15; k++) {
        #pragma unroll
        for (int o = 16; o; o >>= 1) v[k] += __shfl_xor_sync(0xffffffffu, v[k], o);
    }
    if ((tid & 31) == 0) {
        #pragma unroll
        for (int k = 0; k < 15; k++) smr1[half][wih][k] = v[k];
    }
    __syncthreads();
    #pragma unroll
    for (int k = 0; k < 15; k++)
        v[k] = smr1[half][0][k] + smr1[half][1][k] + smr1[half][2][k] + smr1[half][3][k];

    const float sFF0 = v[0], sGG0 = v[1], sFG0 = v[2], sFb0 = v[3], sGb0 = v[4], sbb0 = v[5];
    const float sFF1 = v[6], sGG1 = v[7], sFG1 = v[8], sFb1 = v[9], sGb1 = v[10], sbb1 = v[11];
    const float shh = v[12], sbhbh = v[13], shbh = v[14];

    MS z1 = madds(sFF0, sGG0, sFG0);
    float zcF = z1.m * z1.inv * z1.A, zcG = z1.m * z1.inv * z1.B;
    MS z2 = madds(z1.nc * z1.nc, sbb0, zcF * sFb0 + zcG * sGb0);
    float k2a = z2.m * z2.inv * z2.A, k2b = z2.m * z2.inv * z2.B;
    float facz = fatanh_(z2.nc) * frcp_(z2.nc);
    float zg[2];
    #pragma unroll
    for (int i = 0; i < 2; i++)
        zg[i] = fsigm_(facz * (k2a * (zcF * F0[i] + zcG * G0[i]) + k2b * bzv[i]));

    MS r1 = madds(sFF1, sGG1, sFG1);
    float rcF = r1.m * r1.inv * r1.A, rcG = r1.m * r1.inv * r1.B;
    MS r2 = madds(r1.nc * r1.nc, sbb1, rcF * sFb1 + rcG * sGb1);
    float l2a = r2.m * r2.inv * r2.A, l2b = r2.m * r2.inv * r2.B;
    float facr = fatanh_(r2.nc) * frcp_(r2.nc);
    float rg[2];
    #pragma unroll
    for (int i = 0; i < 2; i++)
        rg[i] = fsigm_(facr * (l2a * (rcF * F1[i] + rcG * G1[i]) + l2b * brv[i]));

    float v2[4] = {0.f, 0.f, 0.f, 0.f};
    #pragma unroll
    for (int i = 0; i < 2; i++) {
        v2[0] = fmaf(rg[i], rg[i], v2[0]);  v2[1] = fmaf(rg[i], bhv[i], v2[1]);
        v2[2] = fmaf(hid[i], rg[i], v2[2]); v2[3] = fmaf(zg[i], zg[i], v2[3]);
    }
    #pragma unroll
    for (int k = 0; k < 4; k++) {
        #pragma unroll
        for (int o = 16; o; o >>= 1) v2[k] += __shfl_xor_sync(0xffffffffu, v2[k], o);
    }
    if ((tid & 31) == 0) {
        #pragma unroll
        for (int k = 0; k < 4; k++) smr2[half][wih][k] = v2[k];
    }
    __syncthreads();
    #pragma unroll
    for (int k = 0; k < 4; k++)
        v2[k] = smr2[half][0][k] + smr2[half][1][k] + smr2[half][2][k] + smr2[half][3][k];
    const float srr = v2[0], srbh = v2[1], shr = v2[2], szz = v2[3];

    MS h3 = madds(srr, sbhbh, srbh);
    float hA = h3.m * h3.inv * h3.A, hB = h3.m * h3.inv * h3.B;
    float sht_h = hA * shr + hB * shbh;
    MS h4 = madds(shh, h3.nc * h3.nc, -sht_h);
    float mA = -h4.m * h4.inv * h4.A;
    float mR =  h4.m * h4.inv * h4.B * hA;
    float mB =  h4.m * h4.inv * h4.B * hB;

    float wx[2];
    float v3[2] = {0.f, 0.f};
    #pragma unroll
    for (int i = 0; i < 2; i++) {
        wx[i] = (mA * hid[i] + mR * rg[i] + mB * bhv[i]) * zg[i];
        v3[0] = fmaf(wx[i], wx[i], v3[0]);
        v3[1] = fmaf(hid[i], wx[i], v3[1]);
    }
    #pragma unroll
    for (int k = 0; k < 2; k++) {
        #pragma unroll
        for (int o = 16; o; o >>= 1) v3[k] += __shfl_xor_sync(0xffffffffu, v3[k], o);
    }
    if ((tid & 31) == 0) {
        #pragma unroll
        for (int k = 0; k < 2; k++) smr3[half][wih][k] = v3[k];
    }
    __syncthreads();
    const float swx  = smr3[half][0][0] + smr3[half][1][0] + smr3[half][2][0] + smr3[half][3][0];
    const float shwx = smr3[half][0][1] + smr3[half][1][1] + smr3[half][2][1] + smr3[half][3][1];

    float xn  = fmaxf(fsqrt_(szz), EPSN);
    float wxn = fmaxf(fsqrt_(swx), EPSN);
    float tt  = fatanh_(fminf(xn, CLIPV));
    float f   = ftanh_(wxn * frcp_(xn) * tt);
    float pn  = fmaxf(f, EPSN);
    float cf  = f * frcp_(wxn);
    if (pn > MAXN) cf *= MAXN * frcp_(pn);
    float pnc = fminf(pn, MAXN);

    MS o5 = madds(shh, pnc * pnc, cf * shwx);
    float oH = o5.m * o5.inv * o5.A, oP = o5.m * o5.inv * o5.B * cf;

    #pragma unroll
    for (int i = 0; i < 2; i++)
        out[b * NB + lt + 128 * i] = oH * hid[i] + oP * wx[i];
}

// ---------------- launch ------------------------------------------------------
extern "C" void kernel_launch(void* const* d_in, const int* in_sizes, int n_in,
                              void* d_out, int out_size)
{
    const float* hyp_x  = (const float*)d_in[0];
    const float* hidden = (const float*)d_in[1];
    const float* Wz_z   = (const float*)d_in[2];
    const float* Wz_r   = (const float*)d_in[3];
    const float* Uz_z   = (const float*)d_in[4];
    const float* Uz_r   = (const float*)d_in[5];
    const float* Wr_z   = (const float*)d_in[6];
    const float* Wr_r   = (const float*)d_in[7];
    const float* Ur_z   = (const float*)d_in[8];
    const float* Ur_r   = (const float*)d_in[9];
    const float* b_z    = (const float*)d_in[14];
    const float* b_r    = (const float*)d_in[15];
    const float* b_h    = (const float*)d_in[16];
    float* out = (float*)d_out;

    cudaFuncSetAttribute(fused_cell, cudaFuncAttributeMaxDynamicSharedMemorySize, SMEM_REQ);
    fused_cell<<<NBLOCKS, 256, SMEM_REQ>>>(hidden, hyp_x, Wz_z, Wz_r, Uz_z, Uz_r,
                                           Wr_z, Wr_r, Ur_z, Ur_r, b_z, b_r, b_h, out);
}